// round 2
// baseline (speedup 1.0000x reference)
#include <cuda_runtime.h>
#include <math.h>

#define HEADS  24
#define HDIM   128
#define BATCH  2
#define TXT    256
#define IMG    1024
#define SEQ    1280          // TXT + IMG
#define DMODEL 3072
#define INNER  3072          // HEADS*HDIM
#define ROWS   (BATCH*SEQ)   // 2560

// ---------------- scratch (static device globals: allowed) ----------------
__device__ float g_x  [ROWS * DMODEL];            // concat input       30 MB
__device__ float g_qkv[ROWS * 3 * INNER];         // qkv gemm out       90 MB
__device__ float g_q  [BATCH * HEADS * SEQ * HDIM]; // 30 MB, [B,H,S,D]
__device__ float g_k  [BATCH * HEADS * SEQ * HDIM];
__device__ float g_v  [BATCH * HEADS * SEQ * HDIM];
__device__ float g_o  [ROWS * INNER];             // attn out [B,S,H*D] 30 MB

// ---------------- 1. concat ----------------
__global__ void concat_kernel(const float* __restrict__ hid,
                              const float* __restrict__ enc) {
    int idx = blockIdx.x * blockDim.x + threadIdx.x;     // float4 index
    const int total = ROWS * DMODEL / 4;
    if (idx >= total) return;
    int row  = idx / (DMODEL / 4);
    int col4 = idx % (DMODEL / 4);
    int b = row / SEQ, s = row % SEQ;
    const float4* src = (s < TXT)
        ? (const float4*)(enc + (size_t)(b * TXT + s) * DMODEL)
        : (const float4*)(hid + (size_t)(b * IMG + (s - TXT)) * DMODEL);
    ((float4*)g_x)[idx] = src[col4];
}

// ---------------- 2/5. SGEMM  C[M,N] = A[M,K] @ B[K,N] + bias ----------------
// BM=BN=128, BK=8, TM=TN=8, 256 threads. REMAP=1 reorders rows for final output.
template <int REMAP>
__global__ __launch_bounds__(256)
void sgemm_bias(int M, int N, int K,
                const float* __restrict__ A, const float* __restrict__ B,
                const float* __restrict__ bias, float* __restrict__ C) {
    const int BM = 128, BN = 128, BK = 8;
    __shared__ float As[BK][BM];   // transposed
    __shared__ float Bs[BK][BN];
    int tid = threadIdx.x;
    int br = blockIdx.y, bc = blockIdx.x;
    const float* Ab = A + (size_t)br * BM * K;
    const float* Bb = B + (size_t)bc * BN;
    int aRow = tid >> 1, aCol = (tid & 1) * 4;
    int bRow = tid >> 5, bCol = (tid & 31) * 4;
    int tr = (tid >> 4) * 8, tc = (tid & 15) * 8;
    float acc[8][8];
    #pragma unroll
    for (int i = 0; i < 8; i++)
        #pragma unroll
        for (int j = 0; j < 8; j++) acc[i][j] = 0.f;

    for (int k0 = 0; k0 < K; k0 += BK) {
        float4 a4 = *(const float4*)(Ab + (size_t)aRow * K + k0 + aCol);
        As[aCol + 0][aRow] = a4.x; As[aCol + 1][aRow] = a4.y;
        As[aCol + 2][aRow] = a4.z; As[aCol + 3][aRow] = a4.w;
        *(float4*)(&Bs[bRow][bCol]) =
            *(const float4*)(Bb + (size_t)(k0 + bRow) * N + bCol);
        __syncthreads();
        #pragma unroll
        for (int k = 0; k < BK; k++) {
            float rm[8], rn[8];
            *(float4*)(rm)     = *(const float4*)(&As[k][tr]);
            *(float4*)(rm + 4) = *(const float4*)(&As[k][tr + 4]);
            *(float4*)(rn)     = *(const float4*)(&Bs[k][tc]);
            *(float4*)(rn + 4) = *(const float4*)(&Bs[k][tc + 4]);
            #pragma unroll
            for (int i = 0; i < 8; i++)
                #pragma unroll
                for (int j = 0; j < 8; j++) acc[i][j] += rm[i] * rn[j];
        }
        __syncthreads();
    }
    #pragma unroll
    for (int i = 0; i < 8; i++) {
        int m = br * BM + tr + i;
        float* crow;
        if (REMAP) {
            int b = m / SEQ, s = m % SEQ;
            int orow = (s < TXT) ? (BATCH * IMG + b * TXT + s)
                                 : (b * IMG + (s - TXT));
            crow = C + (size_t)orow * N;
        } else {
            crow = C + (size_t)m * N;
        }
        #pragma unroll
        for (int j = 0; j < 8; j += 4) {
            int n = bc * 128 + tc + j;
            float4 v;
            v.x = acc[i][j + 0] + bias[n + 0];
            v.y = acc[i][j + 1] + bias[n + 1];
            v.z = acc[i][j + 2] + bias[n + 2];
            v.w = acc[i][j + 3] + bias[n + 3];
            *(float4*)(crow + n) = v;
        }
    }
}

// ---------------- 3. LayerNorm (no affine) + partial RoPE ----------------
// one warp per (b,s,h); handles q,k (LN [+RoPE]) and v (copy).
__global__ void ln_rope_kernel(const float* __restrict__ cosb,
                               const float* __restrict__ sinb) {
    int gw   = (blockIdx.x * blockDim.x + threadIdx.x) >> 5;
    int lane = threadIdx.x & 31;
    if (gw >= BATCH * SEQ * HEADS) return;
    int h = gw % HEADS;
    int s = (gw / HEADS) % SEQ;
    int b = gw / (HEADS * SEQ);
    const float* base = g_qkv + (size_t)(b * SEQ + s) * (3 * INNER) + h * HDIM;
    size_t orow = ((size_t)(b * HEADS + h) * SEQ + s) * HDIM;
    bool img = (s >= TXT);
    float c4[4], s4[4];
    if (img) {
        float4 cv = *(const float4*)(cosb + (size_t)(s - TXT) * HDIM + lane * 4);
        float4 sv = *(const float4*)(sinb + (size_t)(s - TXT) * HDIM + lane * 4);
        c4[0] = cv.x; c4[1] = cv.y; c4[2] = cv.z; c4[3] = cv.w;
        s4[0] = sv.x; s4[1] = sv.y; s4[2] = sv.z; s4[3] = sv.w;
    }
    float sgn = (lane < 16) ? -1.f : 1.f;  // lower half: -imag, upper: +real
    #pragma unroll
    for (int qk = 0; qk < 2; qk++) {
        float4 xv = *(const float4*)(base + qk * INNER + lane * 4);
        float x[4] = {xv.x, xv.y, xv.z, xv.w};
        float sum = x[0] + x[1] + x[2] + x[3];
        #pragma unroll
        for (int o = 16; o > 0; o >>= 1) sum += __shfl_xor_sync(0xffffffffu, sum, o);
        float mu = sum * (1.f / 128.f);
        float vs = 0.f;
        #pragma unroll
        for (int i = 0; i < 4; i++) { float d = x[i] - mu; vs += d * d; x[i] = d; }
        #pragma unroll
        for (int o = 16; o > 0; o >>= 1) vs += __shfl_xor_sync(0xffffffffu, vs, o);
        float inv = rsqrtf(vs * (1.f / 128.f) + 1e-5f);
        #pragma unroll
        for (int i = 0; i < 4; i++) x[i] *= inv;
        if (img) {
            float p[4];
            #pragma unroll
            for (int i = 0; i < 4; i++) p[i] = __shfl_xor_sync(0xffffffffu, x[i], 16);
            #pragma unroll
            for (int i = 0; i < 4; i++) x[i] = x[i] * c4[i] + sgn * p[i] * s4[i];
        }
        float4 ov = {x[0], x[1], x[2], x[3]};
        float* dst = qk == 0 ? g_q : g_k;
        *(float4*)(dst + orow + lane * 4) = ov;
    }
    *(float4*)(g_v + orow + lane * 4) = *(const float4*)(base + 2 * INNER + lane * 4);
}

// ---------------- 4. flash attention (fp32, online softmax) ----------------
// Br=Bc=64, D=128, 256 threads (16x16). grid (20, 24, 2).
#define QPAD 129
#define PPAD 65
__global__ __launch_bounds__(256)
void attn_kernel() {
    extern __shared__ float sm[];
    float* Qs   = sm;                   // 64*129
    float* Ks   = Qs + 64 * QPAD;       // 64*129
    float* Vs   = Ks + 64 * QPAD;       // 64*128
    float* Ps   = Vs + 64 * HDIM;       // 64*65
    float* rowm = Ps + 64 * PPAD;
    float* rowl = rowm + 64;
    float* rowf = rowl + 64;

    int qt = blockIdx.x, h = blockIdx.y, b = blockIdx.z;
    int tid = threadIdx.x;
    int ty = tid >> 4, tx = tid & 15;
    size_t hb = (size_t)(b * HEADS + h) * SEQ * HDIM;
    const float* qb = g_q + hb;
    const float* kb = g_k + hb;
    const float* vb = g_v + hb;

    for (int i = tid; i < 64 * 32; i += 256) {          // 2048 float4
        int r = i >> 5, c4 = i & 31;
        float4 v = *(const float4*)(qb + (size_t)(qt * 64 + r) * HDIM + c4 * 4);
        Qs[r * QPAD + c4 * 4 + 0] = v.x; Qs[r * QPAD + c4 * 4 + 1] = v.y;
        Qs[r * QPAD + c4 * 4 + 2] = v.z; Qs[r * QPAD + c4 * 4 + 3] = v.w;
    }
    if (tid < 64) { rowm[tid] = -INFINITY; rowl[tid] = 0.f; }

    float acc[4][8];
    #pragma unroll
    for (int i = 0; i < 4; i++)
        #pragma unroll
        for (int c = 0; c < 8; c++) acc[i][c] = 0.f;

    const float scale = 0.08838834764831845f;           // 1/sqrt(128)

    for (int kt = 0; kt < SEQ / 64; kt++) {
        for (int i = tid; i < 64 * 32; i += 256) {
            int r = i >> 5, c4 = i & 31;
            float4 kv = *(const float4*)(kb + (size_t)(kt * 64 + r) * HDIM + c4 * 4);
            Ks[r * QPAD + c4 * 4 + 0] = kv.x; Ks[r * QPAD + c4 * 4 + 1] = kv.y;
            Ks[r * QPAD + c4 * 4 + 2] = kv.z; Ks[r * QPAD + c4 * 4 + 3] = kv.w;
            *(float4*)(Vs + r * HDIM + c4 * 4) =
                *(const float4*)(vb + (size_t)(kt * 64 + r) * HDIM + c4 * 4);
        }
        __syncthreads();

        // S = Q @ K^T  (rows ty+16*ii, cols tx+16*jj)
        float sacc[4][4];
        #pragma unroll
        for (int i = 0; i < 4; i++)
            #pragma unroll
            for (int j = 0; j < 4; j++) sacc[i][j] = 0.f;
        #pragma unroll 4
        for (int d = 0; d < HDIM; d++) {
            float qr[4], kr[4];
            #pragma unroll
            for (int ii = 0; ii < 4; ii++) qr[ii] = Qs[(ty + 16 * ii) * QPAD + d];
            #pragma unroll
            for (int jj = 0; jj < 4; jj++) kr[jj] = Ks[(tx + 16 * jj) * QPAD + d];
            #pragma unroll
            for (int ii = 0; ii < 4; ii++)
                #pragma unroll
                for (int jj = 0; jj < 4; jj++) sacc[ii][jj] += qr[ii] * kr[jj];
        }
        #pragma unroll
        for (int ii = 0; ii < 4; ii++)
            #pragma unroll
            for (int jj = 0; jj < 4; jj++)
                Ps[(ty + 16 * ii) * PPAD + tx + 16 * jj] = sacc[ii][jj] * scale;
        __syncthreads();

        // online softmax (one thread per row)
        if (tid < 64) {
            float m_old = rowm[tid];
            float mx = m_old;
            float* pr = Ps + tid * PPAD;
            #pragma unroll 8
            for (int j = 0; j < 64; j++) mx = fmaxf(mx, pr[j]);
            float f = __expf(m_old - mx);
            float sum = 0.f;
            #pragma unroll 8
            for (int j = 0; j < 64; j++) {
                float p = __expf(pr[j] - mx);
                pr[j] = p; sum += p;
            }
            rowl[tid] = rowl[tid] * f + sum;
            rowm[tid] = mx;
            rowf[tid] = f;
        }
        __syncthreads();

        // rescale + O += P @ V  (cols tx+16*cc)
        #pragma unroll
        for (int ii = 0; ii < 4; ii++) {
            float f = rowf[ty + 16 * ii];
            #pragma unroll
            for (int cc = 0; cc < 8; cc++) acc[ii][cc] *= f;
        }
        #pragma unroll 4
        for (int j = 0; j < 64; j++) {
            float pv[4], vv[8];
            #pragma unroll
            for (int ii = 0; ii < 4; ii++) pv[ii] = Ps[(ty + 16 * ii) * PPAD + j];
            #pragma unroll
            for (int cc = 0; cc < 8; cc++) vv[cc] = Vs[j * HDIM + tx + 16 * cc];
            #pragma unroll
            for (int ii = 0; ii < 4; ii++)
                #pragma unroll
                for (int cc = 0; cc < 8; cc++) acc[ii][cc] += pv[ii] * vv[cc];
        }
        __syncthreads();
    }

    // write O as [B, S, H*D]
    float* ob = g_o + ((size_t)b * SEQ + qt * 64) * INNER + h * HDIM;
    #pragma unroll
    for (int ii = 0; ii < 4; ii++) {
        int r = ty + 16 * ii;
        float inv = 1.f / rowl[r];
        #pragma unroll
        for (int cc = 0; cc < 8; cc++)
            ob[(size_t)r * INNER + tx + 16 * cc] = acc[ii][cc] * inv;
    }
}

// ---------------- host ----------------
extern "C" void kernel_launch(void* const* d_in, const int* in_sizes, int n_in,
                              void* d_out, int out_size) {
    const float* hid   = (const float*)d_in[0];
    const float* enc   = (const float*)d_in[1];
    const float* cosb  = (const float*)d_in[2];
    const float* sinb  = (const float*)d_in[3];
    const float* w_qkv = (const float*)d_in[4];
    const float* b_qkv = (const float*)d_in[5];
    const float* w_out = (const float*)d_in[6];
    const float* b_out = (const float*)d_in[7];
    float* out = (float*)d_out;

    float *xp, *qkvp, *op;
    cudaGetSymbolAddress((void**)&xp,   g_x);
    cudaGetSymbolAddress((void**)&qkvp, g_qkv);
    cudaGetSymbolAddress((void**)&op,   g_o);

    // 1. concat
    {
        int total = ROWS * DMODEL / 4;
        concat_kernel<<<(total + 255) / 256, 256>>>(hid, enc);
    }
    // 2. qkv gemm: [2560,3072] @ [3072,9216]
    {
        dim3 grid(3 * INNER / 128, ROWS / 128);
        sgemm_bias<0><<<grid, 256>>>(ROWS, 3 * INNER, DMODEL, xp, w_qkv, b_qkv, qkvp);
    }
    // 3. LN + RoPE
    {
        int warps = BATCH * SEQ * HEADS;
        ln_rope_kernel<<<(warps + 7) / 8, 256>>>(cosb, sinb);
    }
    // 4. attention
    {
        size_t smem = (size_t)(64 * QPAD * 2 + 64 * HDIM + 64 * PPAD + 192) * sizeof(float);
        cudaFuncSetAttribute(attn_kernel, cudaFuncAttributeMaxDynamicSharedMemorySize,
                             (int)smem);
        dim3 grid(SEQ / 64, HEADS, BATCH);
        attn_kernel<<<grid, 256, smem>>>();
    }
    // 5. out proj with row remap: [2560,3072] @ [3072,3072]
    {
        dim3 grid(DMODEL / 128, ROWS / 128);
        sgemm_bias<1><<<grid, 256>>>(ROWS, DMODEL, DMODEL, op, w_out, b_out, out);
    }
}

// round 3
// speedup vs baseline: 1.0519x; 1.0519x over previous
#include <cuda_runtime.h>
#include <math.h>

#define HEADS  24
#define HDIM   128
#define BATCH  2
#define TXT    256
#define IMG    1024
#define SEQ    1280          // TXT + IMG
#define DMODEL 3072
#define INNER  3072          // HEADS*HDIM
#define ROWS   (BATCH*SEQ)   // 2560

// ---------------- scratch (static device globals: allowed) ----------------
__device__ float g_x  [ROWS * DMODEL];            // concat input       30 MB
__device__ float g_qkv[ROWS * 3 * INNER];         // qkv gemm out       90 MB
__device__ float g_q  [BATCH * HEADS * SEQ * HDIM]; // 30 MB, [B,H,S,D]
__device__ float g_k  [BATCH * HEADS * SEQ * HDIM];
__device__ float g_v  [BATCH * HEADS * SEQ * HDIM];
__device__ float g_o  [ROWS * INNER];             // attn out [B,S,H*D] 30 MB

// ---------------- 1. concat ----------------
__global__ void concat_kernel(const float* __restrict__ hid,
                              const float* __restrict__ enc) {
    int idx = blockIdx.x * blockDim.x + threadIdx.x;     // float4 index
    const int total = ROWS * DMODEL / 4;
    if (idx >= total) return;
    int row  = idx / (DMODEL / 4);
    int col4 = idx % (DMODEL / 4);
    int b = row / SEQ, s = row % SEQ;
    const float4* src = (s < TXT)
        ? (const float4*)(enc + (size_t)(b * TXT + s) * DMODEL)
        : (const float4*)(hid + (size_t)(b * IMG + (s - TXT)) * DMODEL);
    ((float4*)g_x)[idx] = src[col4];
}

// ---------------- 2/5. SGEMM  C[M,N] = A[M,K] @ B[K,N] + bias ----------------
// BM=BN=128, BK=8, TM=TN=8, 256 threads. REMAP=1 reorders rows for final output.
template <int REMAP>
__global__ __launch_bounds__(256)
void sgemm_bias(int M, int N, int K,
                const float* __restrict__ A, const float* __restrict__ B,
                const float* __restrict__ bias, float* __restrict__ C) {
    const int BM = 128, BN = 128, BK = 8;
    __shared__ float As[BK][BM];   // transposed
    __shared__ float Bs[BK][BN];
    int tid = threadIdx.x;
    int br = blockIdx.y, bc = blockIdx.x;
    const float* Ab = A + (size_t)br * BM * K;
    const float* Bb = B + (size_t)bc * BN;
    int aRow = tid >> 1, aCol = (tid & 1) * 4;
    int bRow = tid >> 5, bCol = (tid & 31) * 4;
    int tr = (tid >> 4) * 8, tc = (tid & 15) * 8;
    float acc[8][8];
    #pragma unroll
    for (int i = 0; i < 8; i++)
        #pragma unroll
        for (int j = 0; j < 8; j++) acc[i][j] = 0.f;

    for (int k0 = 0; k0 < K; k0 += BK) {
        float4 a4 = *(const float4*)(Ab + (size_t)aRow * K + k0 + aCol);
        As[aCol + 0][aRow] = a4.x; As[aCol + 1][aRow] = a4.y;
        As[aCol + 2][aRow] = a4.z; As[aCol + 3][aRow] = a4.w;
        *(float4*)(&Bs[bRow][bCol]) =
            *(const float4*)(Bb + (size_t)(k0 + bRow) * N + bCol);
        __syncthreads();
        #pragma unroll
        for (int k = 0; k < BK; k++) {
            float rm[8], rn[8];
            *(float4*)(rm)     = *(const float4*)(&As[k][tr]);
            *(float4*)(rm + 4) = *(const float4*)(&As[k][tr + 4]);
            *(float4*)(rn)     = *(const float4*)(&Bs[k][tc]);
            *(float4*)(rn + 4) = *(const float4*)(&Bs[k][tc + 4]);
            #pragma unroll
            for (int i = 0; i < 8; i++)
                #pragma unroll
                for (int j = 0; j < 8; j++) acc[i][j] += rm[i] * rn[j];
        }
        __syncthreads();
    }
    #pragma unroll
    for (int i = 0; i < 8; i++) {
        int m = br * BM + tr + i;
        float* crow;
        if (REMAP) {
            int b = m / SEQ, s = m % SEQ;
            int orow = (s < TXT) ? (BATCH * IMG + b * TXT + s)
                                 : (b * IMG + (s - TXT));
            crow = C + (size_t)orow * N;
        } else {
            crow = C + (size_t)m * N;
        }
        #pragma unroll
        for (int j = 0; j < 8; j += 4) {
            int n = bc * 128 + tc + j;
            float4 v;
            v.x = acc[i][j + 0] + bias[n + 0];
            v.y = acc[i][j + 1] + bias[n + 1];
            v.z = acc[i][j + 2] + bias[n + 2];
            v.w = acc[i][j + 3] + bias[n + 3];
            *(float4*)(crow + n) = v;
        }
    }
}

// ---------------- 3. LayerNorm (no affine) + partial RoPE ----------------
// one warp per (b,s,h); handles q,k (LN [+RoPE]) and v (copy).
__global__ void ln_rope_kernel(const float* __restrict__ cosb,
                               const float* __restrict__ sinb) {
    int gw   = (blockIdx.x * blockDim.x + threadIdx.x) >> 5;
    int lane = threadIdx.x & 31;
    if (gw >= BATCH * SEQ * HEADS) return;
    int h = gw % HEADS;
    int s = (gw / HEADS) % SEQ;
    int b = gw / (HEADS * SEQ);
    const float* base = g_qkv + (size_t)(b * SEQ + s) * (3 * INNER) + h * HDIM;
    size_t orow = ((size_t)(b * HEADS + h) * SEQ + s) * HDIM;
    bool img = (s >= TXT);
    float c4[4], s4[4];
    if (img) {
        float4 cv = *(const float4*)(cosb + (size_t)(s - TXT) * HDIM + lane * 4);
        float4 sv = *(const float4*)(sinb + (size_t)(s - TXT) * HDIM + lane * 4);
        c4[0] = cv.x; c4[1] = cv.y; c4[2] = cv.z; c4[3] = cv.w;
        s4[0] = sv.x; s4[1] = sv.y; s4[2] = sv.z; s4[3] = sv.w;
    }
    float sgn = (lane < 16) ? -1.f : 1.f;  // lower half: -imag, upper: +real
    #pragma unroll
    for (int qk = 0; qk < 2; qk++) {
        float4 xv = *(const float4*)(base + qk * INNER + lane * 4);
        float x[4] = {xv.x, xv.y, xv.z, xv.w};
        float sum = x[0] + x[1] + x[2] + x[3];
        #pragma unroll
        for (int o = 16; o > 0; o >>= 1) sum += __shfl_xor_sync(0xffffffffu, sum, o);
        float mu = sum * (1.f / 128.f);
        float vs = 0.f;
        #pragma unroll
        for (int i = 0; i < 4; i++) { float d = x[i] - mu; vs += d * d; x[i] = d; }
        #pragma unroll
        for (int o = 16; o > 0; o >>= 1) vs += __shfl_xor_sync(0xffffffffu, vs, o);
        float inv = rsqrtf(vs * (1.f / 128.f) + 1e-5f);
        #pragma unroll
        for (int i = 0; i < 4; i++) x[i] *= inv;
        if (img) {
            float p[4];
            #pragma unroll
            for (int i = 0; i < 4; i++) p[i] = __shfl_xor_sync(0xffffffffu, x[i], 16);
            #pragma unroll
            for (int i = 0; i < 4; i++) x[i] = x[i] * c4[i] + sgn * p[i] * s4[i];
        }
        float4 ov = {x[0], x[1], x[2], x[3]};
        float* dst = qk == 0 ? g_q : g_k;
        *(float4*)(dst + orow + lane * 4) = ov;
    }
    *(float4*)(g_v + orow + lane * 4) = *(const float4*)(base + 2 * INNER + lane * 4);
}

// ---------------- 4. flash attention (fp32, online softmax) ----------------
// Br=Bc=64, D=128, 256 threads (16x16). grid (20, 24, 2).
#define QPAD 129
#define PPAD 65
__global__ __launch_bounds__(256)
void attn_kernel() {
    extern __shared__ float sm[];
    float* Qs   = sm;                   // 64*129
    float* Ks   = Qs + 64 * QPAD;       // 64*129
    float* Vs   = Ks + 64 * QPAD;       // 64*128
    float* Ps   = Vs + 64 * HDIM;       // 64*65
    float* rowm = Ps + 64 * PPAD;
    float* rowl = rowm + 64;
    float* rowf = rowl + 64;

    int qt = blockIdx.x, h = blockIdx.y, b = blockIdx.z;
    int tid = threadIdx.x;
    int ty = tid >> 4, tx = tid & 15;
    size_t hb = (size_t)(b * HEADS + h) * SEQ * HDIM;
    const float* qb = g_q + hb;
    const float* kb = g_k + hb;
    const float* vb = g_v + hb;

    for (int i = tid; i < 64 * 32; i += 256) {          // 2048 float4
        int r = i >> 5, c4 = i & 31;
        float4 v = *(const float4*)(qb + (size_t)(qt * 64 + r) * HDIM + c4 * 4);
        Qs[r * QPAD + c4 * 4 + 0] = v.x; Qs[r * QPAD + c4 * 4 + 1] = v.y;
        Qs[r * QPAD + c4 * 4 + 2] = v.z; Qs[r * QPAD + c4 * 4 + 3] = v.w;
    }
    if (tid < 64) { rowm[tid] = -INFINITY; rowl[tid] = 0.f; }

    float acc[4][8];
    #pragma unroll
    for (int i = 0; i < 4; i++)
        #pragma unroll
        for (int c = 0; c < 8; c++) acc[i][c] = 0.f;

    const float scale = 0.08838834764831845f;           // 1/sqrt(128)

    for (int kt = 0; kt < SEQ / 64; kt++) {
        for (int i = tid; i < 64 * 32; i += 256) {
            int r = i >> 5, c4 = i & 31;
            float4 kv = *(const float4*)(kb + (size_t)(kt * 64 + r) * HDIM + c4 * 4);
            Ks[r * QPAD + c4 * 4 + 0] = kv.x; Ks[r * QPAD + c4 * 4 + 1] = kv.y;
            Ks[r * QPAD + c4 * 4 + 2] = kv.z; Ks[r * QPAD + c4 * 4 + 3] = kv.w;
            *(float4*)(Vs + r * HDIM + c4 * 4) =
                *(const float4*)(vb + (size_t)(kt * 64 + r) * HDIM + c4 * 4);
        }
        __syncthreads();

        // S = Q @ K^T  (rows ty+16*ii, cols tx+16*jj)
        float sacc[4][4];
        #pragma unroll
        for (int i = 0; i < 4; i++)
            #pragma unroll
            for (int j = 0; j < 4; j++) sacc[i][j] = 0.f;
        #pragma unroll 4
        for (int d = 0; d < HDIM; d++) {
            float qr[4], kr[4];
            #pragma unroll
            for (int ii = 0; ii < 4; ii++) qr[ii] = Qs[(ty + 16 * ii) * QPAD + d];
            #pragma unroll
            for (int jj = 0; jj < 4; jj++) kr[jj] = Ks[(tx + 16 * jj) * QPAD + d];
            #pragma unroll
            for (int ii = 0; ii < 4; ii++)
                #pragma unroll
                for (int jj = 0; jj < 4; jj++) sacc[ii][jj] += qr[ii] * kr[jj];
        }
        #pragma unroll
        for (int ii = 0; ii < 4; ii++)
            #pragma unroll
            for (int jj = 0; jj < 4; jj++)
                Ps[(ty + 16 * ii) * PPAD + tx + 16 * jj] = sacc[ii][jj] * scale;
        __syncthreads();

        // online softmax (one thread per row)
        if (tid < 64) {
            float m_old = rowm[tid];
            float mx = m_old;
            float* pr = Ps + tid * PPAD;
            #pragma unroll 8
            for (int j = 0; j < 64; j++) mx = fmaxf(mx, pr[j]);
            float f = __expf(m_old - mx);
            float sum = 0.f;
            #pragma unroll 8
            for (int j = 0; j < 64; j++) {
                float p = __expf(pr[j] - mx);
                pr[j] = p; sum += p;
            }
            rowl[tid] = rowl[tid] * f + sum;
            rowm[tid] = mx;
            rowf[tid] = f;
        }
        __syncthreads();

        // rescale + O += P @ V  (cols tx+16*cc)
        #pragma unroll
        for (int ii = 0; ii < 4; ii++) {
            float f = rowf[ty + 16 * ii];
            #pragma unroll
            for (int cc = 0; cc < 8; cc++) acc[ii][cc] *= f;
        }
        #pragma unroll 4
        for (int j = 0; j < 64; j++) {
            float pv[4], vv[8];
            #pragma unroll
            for (int ii = 0; ii < 4; ii++) pv[ii] = Ps[(ty + 16 * ii) * PPAD + j];
            #pragma unroll
            for (int cc = 0; cc < 8; cc++) vv[cc] = Vs[j * HDIM + tx + 16 * cc];
            #pragma unroll
            for (int ii = 0; ii < 4; ii++)
                #pragma unroll
                for (int cc = 0; cc < 8; cc++) acc[ii][cc] += pv[ii] * vv[cc];
        }
        __syncthreads();
    }

    // write O as [B, S, H*D]
    float* ob = g_o + ((size_t)b * SEQ + qt * 64) * INNER + h * HDIM;
    #pragma unroll
    for (int ii = 0; ii < 4; ii++) {
        int r = ty + 16 * ii;
        float inv = 1.f / rowl[r];
        #pragma unroll
        for (int cc = 0; cc < 8; cc++)
            ob[(size_t)r * INNER + tx + 16 * cc] = acc[ii][cc] * inv;
    }
}

// ---------------- host ----------------
extern "C" void kernel_launch(void* const* d_in, const int* in_sizes, int n_in,
                              void* d_out, int out_size) {
    const float* hid   = (const float*)d_in[0];
    const float* enc   = (const float*)d_in[1];
    const float* cosb  = (const float*)d_in[2];
    const float* sinb  = (const float*)d_in[3];
    const float* w_qkv = (const float*)d_in[4];
    const float* b_qkv = (const float*)d_in[5];
    const float* w_out = (const float*)d_in[6];
    const float* b_out = (const float*)d_in[7];
    float* out = (float*)d_out;

    float *xp, *qkvp, *op;
    cudaGetSymbolAddress((void**)&xp,   g_x);
    cudaGetSymbolAddress((void**)&qkvp, g_qkv);
    cudaGetSymbolAddress((void**)&op,   g_o);

    // 1. concat
    {
        int total = ROWS * DMODEL / 4;
        concat_kernel<<<(total + 255) / 256, 256>>>(hid, enc);
    }
    // 2. qkv gemm: [2560,3072] @ [3072,9216]
    {
        dim3 grid(3 * INNER / 128, ROWS / 128);
        sgemm_bias<0><<<grid, 256>>>(ROWS, 3 * INNER, DMODEL, xp, w_qkv, b_qkv, qkvp);
    }
    // 3. LN + RoPE
    {
        int warps = BATCH * SEQ * HEADS;
        ln_rope_kernel<<<(warps + 7) / 8, 256>>>(cosb, sinb);
    }
    // 4. attention
    {
        size_t smem = (size_t)(64 * QPAD * 2 + 64 * HDIM + 64 * PPAD + 192) * sizeof(float);
        cudaFuncSetAttribute(attn_kernel, cudaFuncAttributeMaxDynamicSharedMemorySize,
                             (int)smem);
        dim3 grid(SEQ / 64, HEADS, BATCH);
        attn_kernel<<<grid, 256, smem>>>();
    }
    // 5. out proj with row remap: [2560,3072] @ [3072,3072]
    {
        dim3 grid(DMODEL / 128, ROWS / 128);
        sgemm_bias<1><<<grid, 256>>>(ROWS, DMODEL, DMODEL, op, w_out, b_out, out);
    }
}

// round 4
// speedup vs baseline: 1.7507x; 1.6644x over previous
#include <cuda_runtime.h>
#include <math.h>
#include <stdint.h>

#define HEADS  24
#define HDIM   128
#define BATCH  2
#define TXT    256
#define IMG    1024
#define SEQ    1280          // TXT + IMG
#define DMODEL 3072
#define INNER  3072          // HEADS*HDIM
#define ROWS   (BATCH*SEQ)   // 2560

// ---------------- scratch (static device globals: allowed) ----------------
__device__ float g_x  [ROWS * DMODEL];
__device__ float g_qkv[ROWS * 3 * INNER];
__device__ float g_q  [BATCH * HEADS * SEQ * HDIM];
__device__ float g_k  [BATCH * HEADS * SEQ * HDIM];
__device__ float g_v  [BATCH * HEADS * SEQ * HDIM];
__device__ float g_o  [ROWS * INNER];

// ---------------- 1. concat ----------------
__global__ void concat_kernel(const float* __restrict__ hid,
                              const float* __restrict__ enc) {
    int idx = blockIdx.x * blockDim.x + threadIdx.x;
    const int total = ROWS * DMODEL / 4;
    if (idx >= total) return;
    int row  = idx / (DMODEL / 4);
    int col4 = idx % (DMODEL / 4);
    int b = row / SEQ, s = row % SEQ;
    const float4* src = (s < TXT)
        ? (const float4*)(enc + (size_t)(b * TXT + s) * DMODEL)
        : (const float4*)(hid + (size_t)(b * IMG + (s - TXT)) * DMODEL);
    ((float4*)g_x)[idx] = src[col4];
}

// ---------------- 2/5. TF32 tensor-core GEMM ----------------
// C[M,N] = A[M,K] @ B[K,N] + bias, via mma.sync.m16n8k8.tf32 (fp32 accum).
// BM=BN=128, BK=32, 256 threads (8 warps, warp tile 64x32).
// RNA conversion at smem store (unbiased). Double-buffered smem, padded
// stride 136 (mod 32 == 8 -> conflict-free fragment loads).

__device__ __forceinline__ uint32_t f2tf32(float f) {
    uint32_t u;
    asm("cvt.rna.tf32.f32 %0, %1;" : "=r"(u) : "f"(f));
    return u;
}

#define AST 136
#define BST 136
#define GSTAGE (32 * AST + 32 * BST)   // floats per stage

template <int REMAP>
__global__ __launch_bounds__(256)
void mma_gemm(int M, int N, int K,
              const float* __restrict__ A, const float* __restrict__ B,
              const float* __restrict__ bias, float* __restrict__ C) {
    extern __shared__ float sh[];
    int tid  = threadIdx.x;
    int lane = tid & 31, wid = tid >> 5;
    int wm = wid >> 2;        // 0..1  -> 64 rows of M
    int wn = wid & 3;         // 0..3  -> 32 cols of N
    int bm = blockIdx.y * 128;
    int bn = blockIdx.x * 128;

    const float* Ab = A + (size_t)bm * K;
    const float* Bb = B + bn;

    float acc[4][4][4];
    #pragma unroll
    for (int i = 0; i < 4; i++)
        #pragma unroll
        for (int j = 0; j < 4; j++)
            #pragma unroll
            for (int r = 0; r < 4; r++) acc[i][j][r] = 0.f;

    float4 aR[4], bR[4];

    auto gload = [&](int k0) {
        #pragma unroll
        for (int i = 0; i < 4; i++) {
            int idx = tid + i * 256;
            int ar = idx >> 3, ac4 = idx & 7;
            aR[i] = *(const float4*)(Ab + (size_t)ar * K + k0 + ac4 * 4);
            int brr = idx >> 5, bc4 = idx & 31;
            bR[i] = *(const float4*)(Bb + (size_t)(k0 + brr) * N + bc4 * 4);
        }
    };
    auto sstore = [&](int s) {
        float* As = sh + s * GSTAGE;
        float* Bs = As + 32 * AST;
        #pragma unroll
        for (int i = 0; i < 4; i++) {
            int idx = tid + i * 256;
            int ar = idx >> 3, ac = (idx & 7) * 4;
            As[(ac + 0) * AST + ar] = __uint_as_float(f2tf32(aR[i].x));
            As[(ac + 1) * AST + ar] = __uint_as_float(f2tf32(aR[i].y));
            As[(ac + 2) * AST + ar] = __uint_as_float(f2tf32(aR[i].z));
            As[(ac + 3) * AST + ar] = __uint_as_float(f2tf32(aR[i].w));
            int brr = idx >> 5, bc = (idx & 31) * 4;
            float4 bv;
            bv.x = __uint_as_float(f2tf32(bR[i].x));
            bv.y = __uint_as_float(f2tf32(bR[i].y));
            bv.z = __uint_as_float(f2tf32(bR[i].z));
            bv.w = __uint_as_float(f2tf32(bR[i].w));
            *(float4*)(Bs + brr * BST + bc) = bv;
        }
    };

    gload(0);
    sstore(0);
    __syncthreads();

    int nK = K / 32;
    for (int kt = 0; kt < nK; kt++) {
        int cur = kt & 1;
        if (kt + 1 < nK) gload((kt + 1) * 32);

        const float* As = sh + cur * GSTAGE;
        const float* Bs = As + 32 * AST;
        int mbase = wm * 64 + (lane >> 2);
        int nbase = wn * 32 + (lane >> 2);
        int krow  = lane & 3;

        #pragma unroll
        for (int kk = 0; kk < 32; kk += 8) {
            uint32_t af[4][4], bf[4][2];
            #pragma unroll
            for (int mt = 0; mt < 4; mt++) {
                const float* p  = As + (kk + krow) * AST + mbase + mt * 16;
                const float* p2 = p + 4 * AST;
                af[mt][0] = __float_as_uint(p[0]);
                af[mt][1] = __float_as_uint(p[8]);
                af[mt][2] = __float_as_uint(p2[0]);
                af[mt][3] = __float_as_uint(p2[8]);
            }
            #pragma unroll
            for (int nt = 0; nt < 4; nt++) {
                const float* p = Bs + (kk + krow) * BST + nbase + nt * 8;
                bf[nt][0] = __float_as_uint(p[0]);
                bf[nt][1] = __float_as_uint(p[4 * BST]);
            }
            #pragma unroll
            for (int mt = 0; mt < 4; mt++)
                #pragma unroll
                for (int nt = 0; nt < 4; nt++) {
                    asm volatile(
                        "mma.sync.aligned.m16n8k8.row.col.f32.tf32.tf32.f32 "
                        "{%0,%1,%2,%3}, {%4,%5,%6,%7}, {%8,%9}, {%0,%1,%2,%3};"
                        : "+f"(acc[mt][nt][0]), "+f"(acc[mt][nt][1]),
                          "+f"(acc[mt][nt][2]), "+f"(acc[mt][nt][3])
                        : "r"(af[mt][0]), "r"(af[mt][1]),
                          "r"(af[mt][2]), "r"(af[mt][3]),
                          "r"(bf[nt][0]), "r"(bf[nt][1]));
                }
        }
        if (kt + 1 < nK) sstore(cur ^ 1);
        __syncthreads();
    }

    // epilogue: c0,c1 -> (row, 2c..2c+1), c2,c3 -> (row+8, 2c..2c+1)
    #pragma unroll
    for (int mt = 0; mt < 4; mt++) {
        #pragma unroll
        for (int half = 0; half < 2; half++) {
            int m = bm + wm * 64 + mt * 16 + (lane >> 2) + half * 8;
            float* crow;
            if (REMAP) {
                int b = m / SEQ, s = m % SEQ;
                int orow = (s < TXT) ? (BATCH * IMG + b * TXT + s)
                                     : (b * IMG + (s - TXT));
                crow = C + (size_t)orow * N;
            } else {
                crow = C + (size_t)m * N;
            }
            #pragma unroll
            for (int nt = 0; nt < 4; nt++) {
                int n = bn + wn * 32 + nt * 8 + (lane & 3) * 2;
                float2 v;
                v.x = acc[mt][nt][half * 2 + 0] + bias[n];
                v.y = acc[mt][nt][half * 2 + 1] + bias[n + 1];
                *(float2*)(crow + n) = v;
            }
        }
    }
}

// ---------------- 3. LayerNorm (no affine) + partial RoPE ----------------
__global__ void ln_rope_kernel(const float* __restrict__ cosb,
                               const float* __restrict__ sinb) {
    int gw   = (blockIdx.x * blockDim.x + threadIdx.x) >> 5;
    int lane = threadIdx.x & 31;
    if (gw >= BATCH * SEQ * HEADS) return;
    int h = gw % HEADS;
    int s = (gw / HEADS) % SEQ;
    int b = gw / (HEADS * SEQ);
    const float* base = g_qkv + (size_t)(b * SEQ + s) * (3 * INNER) + h * HDIM;
    size_t orow = ((size_t)(b * HEADS + h) * SEQ + s) * HDIM;
    bool img = (s >= TXT);
    float c4[4], s4[4];
    if (img) {
        float4 cv = *(const float4*)(cosb + (size_t)(s - TXT) * HDIM + lane * 4);
        float4 sv = *(const float4*)(sinb + (size_t)(s - TXT) * HDIM + lane * 4);
        c4[0] = cv.x; c4[1] = cv.y; c4[2] = cv.z; c4[3] = cv.w;
        s4[0] = sv.x; s4[1] = sv.y; s4[2] = sv.z; s4[3] = sv.w;
    }
    float sgn = (lane < 16) ? -1.f : 1.f;
    #pragma unroll
    for (int qk = 0; qk < 2; qk++) {
        float4 xv = *(const float4*)(base + qk * INNER + lane * 4);
        float x[4] = {xv.x, xv.y, xv.z, xv.w};
        float sum = x[0] + x[1] + x[2] + x[3];
        #pragma unroll
        for (int o = 16; o > 0; o >>= 1) sum += __shfl_xor_sync(0xffffffffu, sum, o);
        float mu = sum * (1.f / 128.f);
        float vs = 0.f;
        #pragma unroll
        for (int i = 0; i < 4; i++) { float d = x[i] - mu; vs += d * d; x[i] = d; }
        #pragma unroll
        for (int o = 16; o > 0; o >>= 1) vs += __shfl_xor_sync(0xffffffffu, vs, o);
        float inv = rsqrtf(vs * (1.f / 128.f) + 1e-5f);
        #pragma unroll
        for (int i = 0; i < 4; i++) x[i] *= inv;
        if (img) {
            float p[4];
            #pragma unroll
            for (int i = 0; i < 4; i++) p[i] = __shfl_xor_sync(0xffffffffu, x[i], 16);
            #pragma unroll
            for (int i = 0; i < 4; i++) x[i] = x[i] * c4[i] + sgn * p[i] * s4[i];
        }
        float4 ov = {x[0], x[1], x[2], x[3]};
        float* dst = qk == 0 ? g_q : g_k;
        *(float4*)(dst + orow + lane * 4) = ov;
    }
    *(float4*)(g_v + orow + lane * 4) = *(const float4*)(base + 2 * INNER + lane * 4);
}

// ---------------- 4. flash attention (fp32, online softmax) ----------------
#define QPAD 129
#define PPAD 65
__global__ __launch_bounds__(256)
void attn_kernel() {
    extern __shared__ float sm[];
    float* Qs   = sm;
    float* Ks   = Qs + 64 * QPAD;
    float* Vs   = Ks + 64 * QPAD;
    float* Ps   = Vs + 64 * HDIM;
    float* rowm = Ps + 64 * PPAD;
    float* rowl = rowm + 64;
    float* rowf = rowl + 64;

    int qt = blockIdx.x, h = blockIdx.y, b = blockIdx.z;
    int tid = threadIdx.x;
    int ty = tid >> 4, tx = tid & 15;
    size_t hb = (size_t)(b * HEADS + h) * SEQ * HDIM;
    const float* qb = g_q + hb;
    const float* kb = g_k + hb;
    const float* vb = g_v + hb;

    for (int i = tid; i < 64 * 32; i += 256) {
        int r = i >> 5, c4 = i & 31;
        float4 v = *(const float4*)(qb + (size_t)(qt * 64 + r) * HDIM + c4 * 4);
        Qs[r * QPAD + c4 * 4 + 0] = v.x; Qs[r * QPAD + c4 * 4 + 1] = v.y;
        Qs[r * QPAD + c4 * 4 + 2] = v.z; Qs[r * QPAD + c4 * 4 + 3] = v.w;
    }
    if (tid < 64) { rowm[tid] = -INFINITY; rowl[tid] = 0.f; }

    float acc[4][8];
    #pragma unroll
    for (int i = 0; i < 4; i++)
        #pragma unroll
        for (int c = 0; c < 8; c++) acc[i][c] = 0.f;

    const float scale = 0.08838834764831845f;

    for (int kt = 0; kt < SEQ / 64; kt++) {
        for (int i = tid; i < 64 * 32; i += 256) {
            int r = i >> 5, c4 = i & 31;
            float4 kv = *(const float4*)(kb + (size_t)(kt * 64 + r) * HDIM + c4 * 4);
            Ks[r * QPAD + c4 * 4 + 0] = kv.x; Ks[r * QPAD + c4 * 4 + 1] = kv.y;
            Ks[r * QPAD + c4 * 4 + 2] = kv.z; Ks[r * QPAD + c4 * 4 + 3] = kv.w;
            *(float4*)(Vs + r * HDIM + c4 * 4) =
                *(const float4*)(vb + (size_t)(kt * 64 + r) * HDIM + c4 * 4);
        }
        __syncthreads();

        float sacc[4][4];
        #pragma unroll
        for (int i = 0; i < 4; i++)
            #pragma unroll
            for (int j = 0; j < 4; j++) sacc[i][j] = 0.f;
        #pragma unroll 4
        for (int d = 0; d < HDIM; d++) {
            float qr[4], kr[4];
            #pragma unroll
            for (int ii = 0; ii < 4; ii++) qr[ii] = Qs[(ty + 16 * ii) * QPAD + d];
            #pragma unroll
            for (int jj = 0; jj < 4; jj++) kr[jj] = Ks[(tx + 16 * jj) * QPAD + d];
            #pragma unroll
            for (int ii = 0; ii < 4; ii++)
                #pragma unroll
                for (int jj = 0; jj < 4; jj++) sacc[ii][jj] += qr[ii] * kr[jj];
        }
        #pragma unroll
        for (int ii = 0; ii < 4; ii++)
            #pragma unroll
            for (int jj = 0; jj < 4; jj++)
                Ps[(ty + 16 * ii) * PPAD + tx + 16 * jj] = sacc[ii][jj] * scale;
        __syncthreads();

        if (tid < 64) {
            float m_old = rowm[tid];
            float mx = m_old;
            float* pr = Ps + tid * PPAD;
            #pragma unroll 8
            for (int j = 0; j < 64; j++) mx = fmaxf(mx, pr[j]);
            float f = __expf(m_old - mx);
            float sum = 0.f;
            #pragma unroll 8
            for (int j = 0; j < 64; j++) {
                float p = __expf(pr[j] - mx);
                pr[j] = p; sum += p;
            }
            rowl[tid] = rowl[tid] * f + sum;
            rowm[tid] = mx;
            rowf[tid] = f;
        }
        __syncthreads();

        #pragma unroll
        for (int ii = 0; ii < 4; ii++) {
            float f = rowf[ty + 16 * ii];
            #pragma unroll
            for (int cc = 0; cc < 8; cc++) acc[ii][cc] *= f;
        }
        #pragma unroll 4
        for (int j = 0; j < 64; j++) {
            float pv[4], vv[8];
            #pragma unroll
            for (int ii = 0; ii < 4; ii++) pv[ii] = Ps[(ty + 16 * ii) * PPAD + j];
            #pragma unroll
            for (int cc = 0; cc < 8; cc++) vv[cc] = Vs[j * HDIM + tx + 16 * cc];
            #pragma unroll
            for (int ii = 0; ii < 4; ii++)
                #pragma unroll
                for (int cc = 0; cc < 8; cc++) acc[ii][cc] += pv[ii] * vv[cc];
        }
        __syncthreads();
    }

    float* ob = g_o + ((size_t)b * SEQ + qt * 64) * INNER + h * HDIM;
    #pragma unroll
    for (int ii = 0; ii < 4; ii++) {
        int r = ty + 16 * ii;
        float inv = 1.f / rowl[r];
        #pragma unroll
        for (int cc = 0; cc < 8; cc++)
            ob[(size_t)r * INNER + tx + 16 * cc] = acc[ii][cc] * inv;
    }
}

// ---------------- host ----------------
extern "C" void kernel_launch(void* const* d_in, const int* in_sizes, int n_in,
                              void* d_out, int out_size) {
    const float* hid   = (const float*)d_in[0];
    const float* enc   = (const float*)d_in[1];
    const float* cosb  = (const float*)d_in[2];
    const float* sinb  = (const float*)d_in[3];
    const float* w_qkv = (const float*)d_in[4];
    const float* b_qkv = (const float*)d_in[5];
    const float* w_out = (const float*)d_in[6];
    const float* b_out = (const float*)d_in[7];
    float* out = (float*)d_out;

    float *xp, *qkvp, *op;
    cudaGetSymbolAddress((void**)&xp,   g_x);
    cudaGetSymbolAddress((void**)&qkvp, g_qkv);
    cudaGetSymbolAddress((void**)&op,   g_o);

    const size_t gemm_smem = (size_t)2 * GSTAGE * sizeof(float);  // 69632 B
    static bool attr_set = false;
    if (!attr_set) {
        cudaFuncSetAttribute(mma_gemm<0>, cudaFuncAttributeMaxDynamicSharedMemorySize,
                             (int)gemm_smem);
        cudaFuncSetAttribute(mma_gemm<1>, cudaFuncAttributeMaxDynamicSharedMemorySize,
                             (int)gemm_smem);
        size_t asmem = (size_t)(64 * QPAD * 2 + 64 * HDIM + 64 * PPAD + 192) * sizeof(float);
        cudaFuncSetAttribute(attn_kernel, cudaFuncAttributeMaxDynamicSharedMemorySize,
                             (int)asmem);
        attr_set = true;
    }

    // 1. concat
    {
        int total = ROWS * DMODEL / 4;
        concat_kernel<<<(total + 255) / 256, 256>>>(hid, enc);
    }
    // 2. qkv gemm: [2560,3072] @ [3072,9216]  (tf32 tensor cores)
    {
        dim3 grid(3 * INNER / 128, ROWS / 128);
        mma_gemm<0><<<grid, 256, gemm_smem>>>(ROWS, 3 * INNER, DMODEL,
                                              xp, w_qkv, b_qkv, qkvp);
    }
    // 3. LN + RoPE
    {
        int warps = BATCH * SEQ * HEADS;
        ln_rope_kernel<<<(warps + 7) / 8, 256>>>(cosb, sinb);
    }
    // 4. attention
    {
        size_t smem = (size_t)(64 * QPAD * 2 + 64 * HDIM + 64 * PPAD + 192) * sizeof(float);
        dim3 grid(SEQ / 64, HEADS, BATCH);
        attn_kernel<<<grid, 256, smem>>>();
    }
    // 5. out proj with row remap: [2560,3072] @ [3072,3072]  (tf32 tensor cores)
    {
        dim3 grid(DMODEL / 128, ROWS / 128);
        mma_gemm<1><<<grid, 256, gemm_smem>>>(ROWS, DMODEL, DMODEL,
                                              op, w_out, b_out, out);
    }
}

// round 5
// speedup vs baseline: 2.8679x; 1.6381x over previous
#include <cuda_runtime.h>
#include <math.h>
#include <stdint.h>

#define HEADS  24
#define HDIM   128
#define BATCH  2
#define TXT    256
#define IMG    1024
#define SEQ    1280          // TXT + IMG
#define DMODEL 3072
#define INNER  3072          // HEADS*HDIM
#define ROWS   (BATCH*SEQ)   // 2560

// ---------------- scratch (static device globals: allowed) ----------------
__device__ float g_x  [ROWS * DMODEL];
__device__ float g_qkv[ROWS * 3 * INNER];
__device__ float g_q  [BATCH * HEADS * SEQ * HDIM];
__device__ float g_k  [BATCH * HEADS * SEQ * HDIM];
__device__ float g_v  [BATCH * HEADS * SEQ * HDIM];
__device__ float g_o  [ROWS * INNER];

__device__ __forceinline__ uint32_t f2tf32(float f) {
    uint32_t u;
    asm("cvt.rna.tf32.f32 %0, %1;" : "=r"(u) : "f"(f));
    return u;
}

// ---------------- 1. concat ----------------
__global__ void concat_kernel(const float* __restrict__ hid,
                              const float* __restrict__ enc) {
    int idx = blockIdx.x * blockDim.x + threadIdx.x;
    const int total = ROWS * DMODEL / 4;
    if (idx >= total) return;
    int row  = idx / (DMODEL / 4);
    int col4 = idx % (DMODEL / 4);
    int b = row / SEQ, s = row % SEQ;
    const float4* src = (s < TXT)
        ? (const float4*)(enc + (size_t)(b * TXT + s) * DMODEL)
        : (const float4*)(hid + (size_t)(b * IMG + (s - TXT)) * DMODEL);
    ((float4*)g_x)[idx] = src[col4];
}

// ---------------- 2/5. TF32 tensor-core GEMM ----------------
#define AST 136
#define BST 136
#define GSTAGE (32 * AST + 32 * BST)

template <int REMAP>
__global__ __launch_bounds__(256)
void mma_gemm(int M, int N, int K,
              const float* __restrict__ A, const float* __restrict__ B,
              const float* __restrict__ bias, float* __restrict__ C) {
    extern __shared__ float sh[];
    int tid  = threadIdx.x;
    int lane = tid & 31, wid = tid >> 5;
    int wm = wid >> 2;
    int wn = wid & 3;
    int bm = blockIdx.y * 128;
    int bn = blockIdx.x * 128;

    const float* Ab = A + (size_t)bm * K;
    const float* Bb = B + bn;

    float acc[4][4][4];
    #pragma unroll
    for (int i = 0; i < 4; i++)
        #pragma unroll
        for (int j = 0; j < 4; j++)
            #pragma unroll
            for (int r = 0; r < 4; r++) acc[i][j][r] = 0.f;

    float4 aR[4], bR[4];

    auto gload = [&](int k0) {
        #pragma unroll
        for (int i = 0; i < 4; i++) {
            int idx = tid + i * 256;
            int ar = idx >> 3, ac4 = idx & 7;
            aR[i] = *(const float4*)(Ab + (size_t)ar * K + k0 + ac4 * 4);
            int brr = idx >> 5, bc4 = idx & 31;
            bR[i] = *(const float4*)(Bb + (size_t)(k0 + brr) * N + bc4 * 4);
        }
    };
    auto sstore = [&](int s) {
        float* As = sh + s * GSTAGE;
        float* Bs = As + 32 * AST;
        #pragma unroll
        for (int i = 0; i < 4; i++) {
            int idx = tid + i * 256;
            int ar = idx >> 3, ac = (idx & 7) * 4;
            As[(ac + 0) * AST + ar] = __uint_as_float(f2tf32(aR[i].x));
            As[(ac + 1) * AST + ar] = __uint_as_float(f2tf32(aR[i].y));
            As[(ac + 2) * AST + ar] = __uint_as_float(f2tf32(aR[i].z));
            As[(ac + 3) * AST + ar] = __uint_as_float(f2tf32(aR[i].w));
            int brr = idx >> 5, bc = (idx & 31) * 4;
            float4 bv;
            bv.x = __uint_as_float(f2tf32(bR[i].x));
            bv.y = __uint_as_float(f2tf32(bR[i].y));
            bv.z = __uint_as_float(f2tf32(bR[i].z));
            bv.w = __uint_as_float(f2tf32(bR[i].w));
            *(float4*)(Bs + brr * BST + bc) = bv;
        }
    };

    gload(0);
    sstore(0);
    __syncthreads();

    int nK = K / 32;
    for (int kt = 0; kt < nK; kt++) {
        int cur = kt & 1;
        if (kt + 1 < nK) gload((kt + 1) * 32);

        const float* As = sh + cur * GSTAGE;
        const float* Bs = As + 32 * AST;
        int mbase = wm * 64 + (lane >> 2);
        int nbase = wn * 32 + (lane >> 2);
        int krow  = lane & 3;

        #pragma unroll
        for (int kk = 0; kk < 32; kk += 8) {
            uint32_t af[4][4], bf[4][2];
            #pragma unroll
            for (int mt = 0; mt < 4; mt++) {
                const float* p  = As + (kk + krow) * AST + mbase + mt * 16;
                const float* p2 = p + 4 * AST;
                af[mt][0] = __float_as_uint(p[0]);
                af[mt][1] = __float_as_uint(p[8]);
                af[mt][2] = __float_as_uint(p2[0]);
                af[mt][3] = __float_as_uint(p2[8]);
            }
            #pragma unroll
            for (int nt = 0; nt < 4; nt++) {
                const float* p = Bs + (kk + krow) * BST + nbase + nt * 8;
                bf[nt][0] = __float_as_uint(p[0]);
                bf[nt][1] = __float_as_uint(p[4 * BST]);
            }
            #pragma unroll
            for (int mt = 0; mt < 4; mt++)
                #pragma unroll
                for (int nt = 0; nt < 4; nt++) {
                    asm volatile(
                        "mma.sync.aligned.m16n8k8.row.col.f32.tf32.tf32.f32 "
                        "{%0,%1,%2,%3}, {%4,%5,%6,%7}, {%8,%9}, {%0,%1,%2,%3};"
                        : "+f"(acc[mt][nt][0]), "+f"(acc[mt][nt][1]),
                          "+f"(acc[mt][nt][2]), "+f"(acc[mt][nt][3])
                        : "r"(af[mt][0]), "r"(af[mt][1]),
                          "r"(af[mt][2]), "r"(af[mt][3]),
                          "r"(bf[nt][0]), "r"(bf[nt][1]));
                }
        }
        if (kt + 1 < nK) sstore(cur ^ 1);
        __syncthreads();
    }

    #pragma unroll
    for (int mt = 0; mt < 4; mt++) {
        #pragma unroll
        for (int half = 0; half < 2; half++) {
            int m = bm + wm * 64 + mt * 16 + (lane >> 2) + half * 8;
            float* crow;
            if (REMAP) {
                int b = m / SEQ, s = m % SEQ;
                int orow = (s < TXT) ? (BATCH * IMG + b * TXT + s)
                                     : (b * IMG + (s - TXT));
                crow = C + (size_t)orow * N;
            } else {
                crow = C + (size_t)m * N;
            }
            #pragma unroll
            for (int nt = 0; nt < 4; nt++) {
                int n = bn + wn * 32 + nt * 8 + (lane & 3) * 2;
                float2 v;
                v.x = acc[mt][nt][half * 2 + 0] + bias[n];
                v.y = acc[mt][nt][half * 2 + 1] + bias[n + 1];
                *(float2*)(crow + n) = v;
            }
        }
    }
}

// ---------------- 3. LayerNorm (no affine) + partial RoPE ----------------
__global__ void ln_rope_kernel(const float* __restrict__ cosb,
                               const float* __restrict__ sinb) {
    int gw   = (blockIdx.x * blockDim.x + threadIdx.x) >> 5;
    int lane = threadIdx.x & 31;
    if (gw >= BATCH * SEQ * HEADS) return;
    int h = gw % HEADS;
    int s = (gw / HEADS) % SEQ;
    int b = gw / (HEADS * SEQ);
    const float* base = g_qkv + (size_t)(b * SEQ + s) * (3 * INNER) + h * HDIM;
    size_t orow = ((size_t)(b * HEADS + h) * SEQ + s) * HDIM;
    bool img = (s >= TXT);
    float c4[4], s4[4];
    if (img) {
        float4 cv = *(const float4*)(cosb + (size_t)(s - TXT) * HDIM + lane * 4);
        float4 sv = *(const float4*)(sinb + (size_t)(s - TXT) * HDIM + lane * 4);
        c4[0] = cv.x; c4[1] = cv.y; c4[2] = cv.z; c4[3] = cv.w;
        s4[0] = sv.x; s4[1] = sv.y; s4[2] = sv.z; s4[3] = sv.w;
    }
    float sgn = (lane < 16) ? -1.f : 1.f;
    #pragma unroll
    for (int qk = 0; qk < 2; qk++) {
        float4 xv = *(const float4*)(base + qk * INNER + lane * 4);
        float x[4] = {xv.x, xv.y, xv.z, xv.w};
        float sum = x[0] + x[1] + x[2] + x[3];
        #pragma unroll
        for (int o = 16; o > 0; o >>= 1) sum += __shfl_xor_sync(0xffffffffu, sum, o);
        float mu = sum * (1.f / 128.f);
        float vs = 0.f;
        #pragma unroll
        for (int i = 0; i < 4; i++) { float d = x[i] - mu; vs += d * d; x[i] = d; }
        #pragma unroll
        for (int o = 16; o > 0; o >>= 1) vs += __shfl_xor_sync(0xffffffffu, vs, o);
        float inv = rsqrtf(vs * (1.f / 128.f) + 1e-5f);
        #pragma unroll
        for (int i = 0; i < 4; i++) x[i] *= inv;
        if (img) {
            float p[4];
            #pragma unroll
            for (int i = 0; i < 4; i++) p[i] = __shfl_xor_sync(0xffffffffu, x[i], 16);
            #pragma unroll
            for (int i = 0; i < 4; i++) x[i] = x[i] * c4[i] + sgn * p[i] * s4[i];
        }
        float4 ov = {x[0], x[1], x[2], x[3]};
        float* dst = qk == 0 ? g_q : g_k;
        *(float4*)(dst + orow + lane * 4) = ov;
    }
    *(float4*)(g_v + orow + lane * 4) = *(const float4*)(base + 2 * INNER + lane * 4);
}

// ---------------- 4. flash attention, tf32 tensor cores ----------------
// 128 threads / 4 warps. q-tile 64 (16 rows per warp), kv-tile 64, D=128.
// KST=132 (=4 mod 32), VST=136 (=8 mod 32), PST=68 (=4 mod 32):
// all mma fragment load patterns are bank-conflict-free.
#define KST 132
#define VST 136
#define PST 68
#define ATT_SMEM ((64 * KST + 64 * VST + 4 * 16 * PST) * sizeof(float))

__global__ __launch_bounds__(128)
void attn_tc_kernel() {
    extern __shared__ float sm[];
    float* Ks = sm;                      // Q staging, then K tiles
    float* Vs = Ks + 64 * KST;
    float* Ps = Vs + 64 * VST;           // per-warp 16 x PST

    int qt = blockIdx.x, h = blockIdx.y, b = blockIdx.z;
    int tid = threadIdx.x, lane = tid & 31, wid = tid >> 5;
    size_t hb = (size_t)(b * HEADS + h) * SEQ * HDIM;
    const float* qb = g_q + hb + (size_t)qt * 64 * HDIM;
    const float* kb = g_k + hb;
    const float* vb = g_v + hb;

    // ---- stage Q -> smem (tf32), then extract per-warp fragments ----
    for (int i = tid; i < 64 * 32; i += 128) {
        int r = i >> 5, c4 = i & 31;
        float4 v = *(const float4*)(qb + (size_t)r * HDIM + c4 * 4);
        float* d = Ks + r * KST + c4 * 4;
        d[0] = __uint_as_float(f2tf32(v.x));
        d[1] = __uint_as_float(f2tf32(v.y));
        d[2] = __uint_as_float(f2tf32(v.z));
        d[3] = __uint_as_float(f2tf32(v.w));
    }
    __syncthreads();

    uint32_t qf[16][4];
    {
        const float* p0 = Ks + (wid * 16 + (lane >> 2)) * KST + (lane & 3);
        #pragma unroll
        for (int kk = 0; kk < 16; kk++) {
            qf[kk][0] = __float_as_uint(p0[kk * 8]);
            qf[kk][1] = __float_as_uint(p0[8 * KST + kk * 8]);
            qf[kk][2] = __float_as_uint(p0[kk * 8 + 4]);
            qf[kk][3] = __float_as_uint(p0[8 * KST + kk * 8 + 4]);
        }
    }
    __syncthreads();

    float oacc[16][4];
    #pragma unroll
    for (int nt = 0; nt < 16; nt++)
        #pragma unroll
        for (int r = 0; r < 4; r++) oacc[nt][r] = 0.f;

    float m_lo = -INFINITY, m_hi = -INFINITY, l_lo = 0.f, l_hi = 0.f;
    const float scale = 0.08838834764831845f;
    float* Pw = Ps + wid * 16 * PST;

    for (int kt = 0; kt < SEQ / 64; kt++) {
        // ---- load K, V tiles (tf32) ----
        for (int i = tid; i < 64 * 32; i += 128) {
            int r = i >> 5, c4 = i & 31;
            float4 kv4 = *(const float4*)(kb + (size_t)(kt * 64 + r) * HDIM + c4 * 4);
            float* dk = Ks + r * KST + c4 * 4;
            dk[0] = __uint_as_float(f2tf32(kv4.x));
            dk[1] = __uint_as_float(f2tf32(kv4.y));
            dk[2] = __uint_as_float(f2tf32(kv4.z));
            dk[3] = __uint_as_float(f2tf32(kv4.w));
            float4 vv4 = *(const float4*)(vb + (size_t)(kt * 64 + r) * HDIM + c4 * 4);
            float* dv = Vs + r * VST + c4 * 4;
            dv[0] = __uint_as_float(f2tf32(vv4.x));
            dv[1] = __uint_as_float(f2tf32(vv4.y));
            dv[2] = __uint_as_float(f2tf32(vv4.z));
            dv[3] = __uint_as_float(f2tf32(vv4.w));
        }
        __syncthreads();

        // ---- S = Q @ K^T (16 x 64 per warp) ----
        float sacc[8][4];
        #pragma unroll
        for (int nt = 0; nt < 8; nt++)
            #pragma unroll
            for (int r = 0; r < 4; r++) sacc[nt][r] = 0.f;

        #pragma unroll
        for (int kk = 0; kk < 16; kk++) {
            uint32_t bf[8][2];
            #pragma unroll
            for (int nt = 0; nt < 8; nt++) {
                const float* p = Ks + (nt * 8 + (lane >> 2)) * KST + kk * 8 + (lane & 3);
                bf[nt][0] = __float_as_uint(p[0]);
                bf[nt][1] = __float_as_uint(p[4]);
            }
            #pragma unroll
            for (int nt = 0; nt < 8; nt++) {
                asm volatile(
                    "mma.sync.aligned.m16n8k8.row.col.f32.tf32.tf32.f32 "
                    "{%0,%1,%2,%3}, {%4,%5,%6,%7}, {%8,%9}, {%0,%1,%2,%3};"
                    : "+f"(sacc[nt][0]), "+f"(sacc[nt][1]),
                      "+f"(sacc[nt][2]), "+f"(sacc[nt][3])
                    : "r"(qf[kk][0]), "r"(qf[kk][1]),
                      "r"(qf[kk][2]), "r"(qf[kk][3]),
                      "r"(bf[nt][0]), "r"(bf[nt][1]));
            }
        }

        // ---- online softmax in registers ----
        float mx_lo = m_lo, mx_hi = m_hi;
        #pragma unroll
        for (int nt = 0; nt < 8; nt++) {
            sacc[nt][0] *= scale; sacc[nt][1] *= scale;
            sacc[nt][2] *= scale; sacc[nt][3] *= scale;
            mx_lo = fmaxf(mx_lo, fmaxf(sacc[nt][0], sacc[nt][1]));
            mx_hi = fmaxf(mx_hi, fmaxf(sacc[nt][2], sacc[nt][3]));
        }
        #pragma unroll
        for (int o = 1; o <= 2; o <<= 1) {
            mx_lo = fmaxf(mx_lo, __shfl_xor_sync(0xffffffffu, mx_lo, o));
            mx_hi = fmaxf(mx_hi, __shfl_xor_sync(0xffffffffu, mx_hi, o));
        }
        float f_lo = __expf(m_lo - mx_lo);
        float f_hi = __expf(m_hi - mx_hi);
        float sum_lo = 0.f, sum_hi = 0.f;
        #pragma unroll
        for (int nt = 0; nt < 8; nt++) {
            float p0 = __expf(sacc[nt][0] - mx_lo);
            float p1 = __expf(sacc[nt][1] - mx_lo);
            float p2 = __expf(sacc[nt][2] - mx_hi);
            float p3 = __expf(sacc[nt][3] - mx_hi);
            sum_lo += p0 + p1; sum_hi += p2 + p3;
            int col = nt * 8 + 2 * (lane & 3);
            float2 w0 = {__uint_as_float(f2tf32(p0)), __uint_as_float(f2tf32(p1))};
            float2 w1 = {__uint_as_float(f2tf32(p2)), __uint_as_float(f2tf32(p3))};
            *(float2*)(Pw + (lane >> 2) * PST + col) = w0;
            *(float2*)(Pw + ((lane >> 2) + 8) * PST + col) = w1;
        }
        #pragma unroll
        for (int o = 1; o <= 2; o <<= 1) {
            sum_lo += __shfl_xor_sync(0xffffffffu, sum_lo, o);
            sum_hi += __shfl_xor_sync(0xffffffffu, sum_hi, o);
        }
        l_lo = l_lo * f_lo + sum_lo;
        l_hi = l_hi * f_hi + sum_hi;
        m_lo = mx_lo; m_hi = mx_hi;
        __syncwarp();

        // ---- rescale O, then O += P @ V ----
        #pragma unroll
        for (int nt = 0; nt < 16; nt++) {
            oacc[nt][0] *= f_lo; oacc[nt][1] *= f_lo;
            oacc[nt][2] *= f_hi; oacc[nt][3] *= f_hi;
        }
        #pragma unroll
        for (int kk = 0; kk < 8; kk++) {
            uint32_t af[4];
            const float* pa = Pw + (lane >> 2) * PST + kk * 8 + (lane & 3);
            af[0] = __float_as_uint(pa[0]);
            af[1] = __float_as_uint(pa[8 * PST]);
            af[2] = __float_as_uint(pa[4]);
            af[3] = __float_as_uint(pa[8 * PST + 4]);
            const float* vrow0 = Vs + (kk * 8 + (lane & 3)) * VST + (lane >> 2);
            const float* vrow1 = vrow0 + 4 * VST;
            #pragma unroll
            for (int nt = 0; nt < 16; nt++) {
                uint32_t b0 = __float_as_uint(vrow0[nt * 8]);
                uint32_t b1 = __float_as_uint(vrow1[nt * 8]);
                asm volatile(
                    "mma.sync.aligned.m16n8k8.row.col.f32.tf32.tf32.f32 "
                    "{%0,%1,%2,%3}, {%4,%5,%6,%7}, {%8,%9}, {%0,%1,%2,%3};"
                    : "+f"(oacc[nt][0]), "+f"(oacc[nt][1]),
                      "+f"(oacc[nt][2]), "+f"(oacc[nt][3])
                    : "r"(af[0]), "r"(af[1]), "r"(af[2]), "r"(af[3]),
                      "r"(b0), "r"(b1));
            }
        }
        __syncthreads();
    }

    // ---- epilogue ----
    float inv_lo = 1.f / l_lo, inv_hi = 1.f / l_hi;
    int r = qt * 64 + wid * 16 + (lane >> 2);
    float* ob0 = g_o + ((size_t)b * SEQ + r) * INNER + h * HDIM;
    float* ob1 = g_o + ((size_t)b * SEQ + r + 8) * INNER + h * HDIM;
    #pragma unroll
    for (int nt = 0; nt < 16; nt++) {
        int col = nt * 8 + 2 * (lane & 3);
        float2 v0 = {oacc[nt][0] * inv_lo, oacc[nt][1] * inv_lo};
        float2 v1 = {oacc[nt][2] * inv_hi, oacc[nt][3] * inv_hi};
        *(float2*)(ob0 + col) = v0;
        *(float2*)(ob1 + col) = v1;
    }
}

// ---------------- host ----------------
extern "C" void kernel_launch(void* const* d_in, const int* in_sizes, int n_in,
                              void* d_out, int out_size) {
    const float* hid   = (const float*)d_in[0];
    const float* enc   = (const float*)d_in[1];
    const float* cosb  = (const float*)d_in[2];
    const float* sinb  = (const float*)d_in[3];
    const float* w_qkv = (const float*)d_in[4];
    const float* b_qkv = (const float*)d_in[5];
    const float* w_out = (const float*)d_in[6];
    const float* b_out = (const float*)d_in[7];
    float* out = (float*)d_out;

    float *xp, *qkvp, *op;
    cudaGetSymbolAddress((void**)&xp,   g_x);
    cudaGetSymbolAddress((void**)&qkvp, g_qkv);
    cudaGetSymbolAddress((void**)&op,   g_o);

    const size_t gemm_smem = (size_t)2 * GSTAGE * sizeof(float);
    static bool attr_set = false;
    if (!attr_set) {
        cudaFuncSetAttribute(mma_gemm<0>, cudaFuncAttributeMaxDynamicSharedMemorySize,
                             (int)gemm_smem);
        cudaFuncSetAttribute(mma_gemm<1>, cudaFuncAttributeMaxDynamicSharedMemorySize,
                             (int)gemm_smem);
        cudaFuncSetAttribute(attn_tc_kernel, cudaFuncAttributeMaxDynamicSharedMemorySize,
                             (int)ATT_SMEM);
        attr_set = true;
    }

    // 1. concat
    {
        int total = ROWS * DMODEL / 4;
        concat_kernel<<<(total + 255) / 256, 256>>>(hid, enc);
    }
    // 2. qkv gemm (tf32 tensor cores)
    {
        dim3 grid(3 * INNER / 128, ROWS / 128);
        mma_gemm<0><<<grid, 256, gemm_smem>>>(ROWS, 3 * INNER, DMODEL,
                                              xp, w_qkv, b_qkv, qkvp);
    }
    // 3. LN + RoPE
    {
        int warps = BATCH * SEQ * HEADS;
        ln_rope_kernel<<<(warps + 7) / 8, 256>>>(cosb, sinb);
    }
    // 4. attention (tf32 tensor cores)
    {
        dim3 grid(SEQ / 64, HEADS, BATCH);
        attn_tc_kernel<<<grid, 128, ATT_SMEM>>>();
    }
    // 5. out proj with row remap (tf32 tensor cores)
    {
        dim3 grid(DMODEL / 128, ROWS / 128);
        mma_gemm<1><<<grid, 256, gemm_smem>>>(ROWS, DMODEL, DMODEL,
                                              op, w_out, b_out, out);
    }
}

// round 6
// speedup vs baseline: 4.1374x; 1.4427x over previous
#include <cuda_runtime.h>
#include <math.h>
#include <stdint.h>

#define HEADS  24
#define HDIM   128
#define BATCH  2
#define TXT    256
#define IMG    1024
#define SEQ    1280          // TXT + IMG
#define DMODEL 3072
#define INNER  3072          // HEADS*HDIM
#define ROWS   (BATCH*SEQ)   // 2560

// ---------------- scratch (static device globals: allowed) ----------------
__device__ float g_x  [ROWS * DMODEL];            // tf32-rounded concat
__device__ float g_qkv[ROWS * 3 * INNER];
__device__ float g_q  [BATCH * HEADS * SEQ * HDIM]; // tf32-rounded
__device__ float g_k  [BATCH * HEADS * SEQ * HDIM]; // tf32-rounded
__device__ float g_v  [BATCH * HEADS * SEQ * HDIM]; // tf32-rounded
__device__ float g_o  [ROWS * INNER];             // tf32-rounded attn out
__device__ float g_wq [DMODEL * 3 * INNER];       // tf32-rounded w_qkv
__device__ float g_wo [INNER * DMODEL];           // tf32-rounded w_out

__device__ __forceinline__ uint32_t f2tf32(float f) {
    uint32_t u;
    asm("cvt.rna.tf32.f32 %0, %1;" : "=r"(u) : "f"(f));
    return u;
}
__device__ __forceinline__ float rtf(float f) {
    return __uint_as_float(f2tf32(f));
}

// ---------------- 0. weight rounding ----------------
__global__ void cvtw_kernel(const float* __restrict__ src, float* __restrict__ dst,
                            int n4) {
    int idx = blockIdx.x * blockDim.x + threadIdx.x;
    if (idx >= n4) return;
    float4 v = ((const float4*)src)[idx];
    v.x = rtf(v.x); v.y = rtf(v.y); v.z = rtf(v.z); v.w = rtf(v.w);
    ((float4*)dst)[idx] = v;
}

// ---------------- 1. concat (+ tf32 round) ----------------
__global__ void concat_kernel(const float* __restrict__ hid,
                              const float* __restrict__ enc) {
    int idx = blockIdx.x * blockDim.x + threadIdx.x;
    const int total = ROWS * DMODEL / 4;
    if (idx >= total) return;
    int row  = idx / (DMODEL / 4);
    int col4 = idx % (DMODEL / 4);
    int b = row / SEQ, s = row % SEQ;
    const float4* src = (s < TXT)
        ? (const float4*)(enc + (size_t)(b * TXT + s) * DMODEL)
        : (const float4*)(hid + (size_t)(b * IMG + (s - TXT)) * DMODEL);
    float4 v = src[col4];
    v.x = rtf(v.x); v.y = rtf(v.y); v.z = rtf(v.z); v.w = rtf(v.w);
    ((float4*)g_x)[idx] = v;
}

// ---------------- 2/5. TF32 tensor-core GEMM, cp.async 2-stage ----------------
// Inputs already tf32-rounded -> no conversion anywhere in the kernel.
// A row-major [m][ASTRIDE], B row-major [k][BSTRIDE]; both fragment
// patterns enumerate all 32 banks (stride 36 / 136) -> conflict-free.
#define ASTRIDE 36
#define BSTRIDE 136
#define STAGE_A (128 * ASTRIDE)          // 4608 floats
#define STAGE_B (32 * BSTRIDE)           // 4352 floats
#define STAGE   (STAGE_A + STAGE_B)      // 8960 floats = 35840 B
#define GEMM_SMEM ((size_t)2 * STAGE * sizeof(float))   // 71680 B

template <int REMAP>
__global__ __launch_bounds__(256, 2)
void mma_gemm(int M, int N, int K,
              const float* __restrict__ A, const float* __restrict__ B,
              const float* __restrict__ bias, float* __restrict__ C) {
    extern __shared__ float sh[];
    int tid  = threadIdx.x;
    int lane = tid & 31, wid = tid >> 5;
    int wm = wid >> 2;        // 0..1 -> 64 rows
    int wn = wid & 3;         // 0..3 -> 32 cols
    int bm = blockIdx.y * 128;
    int bn = blockIdx.x * 128;

    const float* Ab = A + (size_t)bm * K;
    const float* Bb = B + bn;

    float acc[4][4][4];
    #pragma unroll
    for (int i = 0; i < 4; i++)
        #pragma unroll
        for (int j = 0; j < 4; j++)
            #pragma unroll
            for (int r = 0; r < 4; r++) acc[i][j][r] = 0.f;

    auto copy_tile = [&](int k0, int s) {
        float* As = sh + s * STAGE;
        float* Bs = As + STAGE_A;
        #pragma unroll
        for (int i = 0; i < 4; i++) {
            int idx = tid + i * 256;
            int ar = idx >> 3, ac4 = idx & 7;
            uint32_t da = (uint32_t)__cvta_generic_to_shared(
                As + ar * ASTRIDE + ac4 * 4);
            const float* sa = Ab + (size_t)ar * K + k0 + ac4 * 4;
            asm volatile("cp.async.cg.shared.global [%0], [%1], 16;"
                         :: "r"(da), "l"(sa));
            int brr = idx >> 5, bc4 = idx & 31;
            uint32_t db = (uint32_t)__cvta_generic_to_shared(
                Bs + brr * BSTRIDE + bc4 * 4);
            const float* sb = Bb + (size_t)(k0 + brr) * N + bc4 * 4;
            asm volatile("cp.async.cg.shared.global [%0], [%1], 16;"
                         :: "r"(db), "l"(sb));
        }
        asm volatile("cp.async.commit_group;");
    };

    copy_tile(0, 0);
    int nK = K / 32;

    for (int kt = 0; kt < nK; kt++) {
        asm volatile("cp.async.wait_group 0;");
        __syncthreads();
        if (kt + 1 < nK) copy_tile((kt + 1) * 32, (kt + 1) & 1);

        const float* As = sh + (kt & 1) * STAGE;
        const float* Bs = As + STAGE_A;
        int r4 = lane >> 2, kc = lane & 3;

        #pragma unroll
        for (int kk = 0; kk < 4; kk++) {
            uint32_t af[4][4], bf[4][2];
            #pragma unroll
            for (int mt = 0; mt < 4; mt++) {
                const float* pa = As + (wm * 64 + mt * 16 + r4) * ASTRIDE + kk * 8 + kc;
                af[mt][0] = __float_as_uint(pa[0]);
                af[mt][1] = __float_as_uint(pa[8 * ASTRIDE]);
                af[mt][2] = __float_as_uint(pa[4]);
                af[mt][3] = __float_as_uint(pa[8 * ASTRIDE + 4]);
            }
            #pragma unroll
            for (int nt = 0; nt < 4; nt++) {
                const float* pb = Bs + (kk * 8 + kc) * BSTRIDE + wn * 32 + nt * 8 + r4;
                bf[nt][0] = __float_as_uint(pb[0]);
                bf[nt][1] = __float_as_uint(pb[4 * BSTRIDE]);
            }
            #pragma unroll
            for (int mt = 0; mt < 4; mt++)
                #pragma unroll
                for (int nt = 0; nt < 4; nt++) {
                    asm volatile(
                        "mma.sync.aligned.m16n8k8.row.col.f32.tf32.tf32.f32 "
                        "{%0,%1,%2,%3}, {%4,%5,%6,%7}, {%8,%9}, {%0,%1,%2,%3};"
                        : "+f"(acc[mt][nt][0]), "+f"(acc[mt][nt][1]),
                          "+f"(acc[mt][nt][2]), "+f"(acc[mt][nt][3])
                        : "r"(af[mt][0]), "r"(af[mt][1]),
                          "r"(af[mt][2]), "r"(af[mt][3]),
                          "r"(bf[nt][0]), "r"(bf[nt][1]));
                }
        }
        __syncthreads();
    }

    #pragma unroll
    for (int mt = 0; mt < 4; mt++) {
        #pragma unroll
        for (int half = 0; half < 2; half++) {
            int m = bm + wm * 64 + mt * 16 + (lane >> 2) + half * 8;
            float* crow;
            if (REMAP) {
                int b = m / SEQ, s = m % SEQ;
                int orow = (s < TXT) ? (BATCH * IMG + b * TXT + s)
                                     : (b * IMG + (s - TXT));
                crow = C + (size_t)orow * N;
            } else {
                crow = C + (size_t)m * N;
            }
            #pragma unroll
            for (int nt = 0; nt < 4; nt++) {
                int n = bn + wn * 32 + nt * 8 + (lane & 3) * 2;
                float2 v;
                v.x = acc[mt][nt][half * 2 + 0] + bias[n];
                v.y = acc[mt][nt][half * 2 + 1] + bias[n + 1];
                *(float2*)(crow + n) = v;
            }
        }
    }
}

// ---------------- 3. LayerNorm + partial RoPE (+ tf32 round q/k/v) ----------
__global__ void ln_rope_kernel(const float* __restrict__ cosb,
                               const float* __restrict__ sinb) {
    int gw   = (blockIdx.x * blockDim.x + threadIdx.x) >> 5;
    int lane = threadIdx.x & 31;
    if (gw >= BATCH * SEQ * HEADS) return;
    int h = gw % HEADS;
    int s = (gw / HEADS) % SEQ;
    int b = gw / (HEADS * SEQ);
    const float* base = g_qkv + (size_t)(b * SEQ + s) * (3 * INNER) + h * HDIM;
    size_t orow = ((size_t)(b * HEADS + h) * SEQ + s) * HDIM;
    bool img = (s >= TXT);
    float c4[4], s4[4];
    if (img) {
        float4 cv = *(const float4*)(cosb + (size_t)(s - TXT) * HDIM + lane * 4);
        float4 sv = *(const float4*)(sinb + (size_t)(s - TXT) * HDIM + lane * 4);
        c4[0] = cv.x; c4[1] = cv.y; c4[2] = cv.z; c4[3] = cv.w;
        s4[0] = sv.x; s4[1] = sv.y; s4[2] = sv.z; s4[3] = sv.w;
    }
    float sgn = (lane < 16) ? -1.f : 1.f;
    #pragma unroll
    for (int qk = 0; qk < 2; qk++) {
        float4 xv = *(const float4*)(base + qk * INNER + lane * 4);
        float x[4] = {xv.x, xv.y, xv.z, xv.w};
        float sum = x[0] + x[1] + x[2] + x[3];
        #pragma unroll
        for (int o = 16; o > 0; o >>= 1) sum += __shfl_xor_sync(0xffffffffu, sum, o);
        float mu = sum * (1.f / 128.f);
        float vs = 0.f;
        #pragma unroll
        for (int i = 0; i < 4; i++) { float d = x[i] - mu; vs += d * d; x[i] = d; }
        #pragma unroll
        for (int o = 16; o > 0; o >>= 1) vs += __shfl_xor_sync(0xffffffffu, vs, o);
        float inv = rsqrtf(vs * (1.f / 128.f) + 1e-5f);
        #pragma unroll
        for (int i = 0; i < 4; i++) x[i] *= inv;
        if (img) {
            float p[4];
            #pragma unroll
            for (int i = 0; i < 4; i++) p[i] = __shfl_xor_sync(0xffffffffu, x[i], 16);
            #pragma unroll
            for (int i = 0; i < 4; i++) x[i] = x[i] * c4[i] + sgn * p[i] * s4[i];
        }
        float4 ov = {rtf(x[0]), rtf(x[1]), rtf(x[2]), rtf(x[3])};
        float* dst = qk == 0 ? g_q : g_k;
        *(float4*)(dst + orow + lane * 4) = ov;
    }
    {
        float4 vv = *(const float4*)(base + 2 * INNER + lane * 4);
        vv.x = rtf(vv.x); vv.y = rtf(vv.y); vv.z = rtf(vv.z); vv.w = rtf(vv.w);
        *(float4*)(g_v + orow + lane * 4) = vv;
    }
}

// ---------------- 4. flash attention, tf32 tensor cores ----------------
// q/k/v pre-rounded to tf32 -> no conversion in the loops (only P).
#define KST 132
#define VST 136
#define PST 68
#define ATT_SMEM ((64 * KST + 64 * VST + 4 * 16 * PST) * sizeof(float))

__global__ __launch_bounds__(128)
void attn_tc_kernel() {
    extern __shared__ float sm[];
    float* Ks = sm;
    float* Vs = Ks + 64 * KST;
    float* Ps = Vs + 64 * VST;

    int qt = blockIdx.x, h = blockIdx.y, b = blockIdx.z;
    int tid = threadIdx.x, lane = tid & 31, wid = tid >> 5;
    size_t hb = (size_t)(b * HEADS + h) * SEQ * HDIM;
    const float* qb = g_q + hb + (size_t)qt * 64 * HDIM;
    const float* kb = g_k + hb;
    const float* vb = g_v + hb;

    for (int i = tid; i < 64 * 32; i += 128) {
        int r = i >> 5, c4 = i & 31;
        *(float4*)(Ks + r * KST + c4 * 4) =
            *(const float4*)(qb + (size_t)r * HDIM + c4 * 4);
    }
    __syncthreads();

    uint32_t qf[16][4];
    {
        const float* p0 = Ks + (wid * 16 + (lane >> 2)) * KST + (lane & 3);
        #pragma unroll
        for (int kk = 0; kk < 16; kk++) {
            qf[kk][0] = __float_as_uint(p0[kk * 8]);
            qf[kk][1] = __float_as_uint(p0[8 * KST + kk * 8]);
            qf[kk][2] = __float_as_uint(p0[kk * 8 + 4]);
            qf[kk][3] = __float_as_uint(p0[8 * KST + kk * 8 + 4]);
        }
    }
    __syncthreads();

    float oacc[16][4];
    #pragma unroll
    for (int nt = 0; nt < 16; nt++)
        #pragma unroll
        for (int r = 0; r < 4; r++) oacc[nt][r] = 0.f;

    float m_lo = -INFINITY, m_hi = -INFINITY, l_lo = 0.f, l_hi = 0.f;
    const float scale = 0.08838834764831845f;
    float* Pw = Ps + wid * 16 * PST;

    for (int kt = 0; kt < SEQ / 64; kt++) {
        for (int i = tid; i < 64 * 32; i += 128) {
            int r = i >> 5, c4 = i & 31;
            *(float4*)(Ks + r * KST + c4 * 4) =
                *(const float4*)(kb + (size_t)(kt * 64 + r) * HDIM + c4 * 4);
            *(float4*)(Vs + r * VST + c4 * 4) =
                *(const float4*)(vb + (size_t)(kt * 64 + r) * HDIM + c4 * 4);
        }
        __syncthreads();

        float sacc[8][4];
        #pragma unroll
        for (int nt = 0; nt < 8; nt++)
            #pragma unroll
            for (int r = 0; r < 4; r++) sacc[nt][r] = 0.f;

        #pragma unroll
        for (int kk = 0; kk < 16; kk++) {
            uint32_t bf[8][2];
            #pragma unroll
            for (int nt = 0; nt < 8; nt++) {
                const float* p = Ks + (nt * 8 + (lane >> 2)) * KST + kk * 8 + (lane & 3);
                bf[nt][0] = __float_as_uint(p[0]);
                bf[nt][1] = __float_as_uint(p[4]);
            }
            #pragma unroll
            for (int nt = 0; nt < 8; nt++) {
                asm volatile(
                    "mma.sync.aligned.m16n8k8.row.col.f32.tf32.tf32.f32 "
                    "{%0,%1,%2,%3}, {%4,%5,%6,%7}, {%8,%9}, {%0,%1,%2,%3};"
                    : "+f"(sacc[nt][0]), "+f"(sacc[nt][1]),
                      "+f"(sacc[nt][2]), "+f"(sacc[nt][3])
                    : "r"(qf[kk][0]), "r"(qf[kk][1]),
                      "r"(qf[kk][2]), "r"(qf[kk][3]),
                      "r"(bf[nt][0]), "r"(bf[nt][1]));
            }
        }

        float mx_lo = m_lo, mx_hi = m_hi;
        #pragma unroll
        for (int nt = 0; nt < 8; nt++) {
            sacc[nt][0] *= scale; sacc[nt][1] *= scale;
            sacc[nt][2] *= scale; sacc[nt][3] *= scale;
            mx_lo = fmaxf(mx_lo, fmaxf(sacc[nt][0], sacc[nt][1]));
            mx_hi = fmaxf(mx_hi, fmaxf(sacc[nt][2], sacc[nt][3]));
        }
        #pragma unroll
        for (int o = 1; o <= 2; o <<= 1) {
            mx_lo = fmaxf(mx_lo, __shfl_xor_sync(0xffffffffu, mx_lo, o));
            mx_hi = fmaxf(mx_hi, __shfl_xor_sync(0xffffffffu, mx_hi, o));
        }
        float f_lo = __expf(m_lo - mx_lo);
        float f_hi = __expf(m_hi - mx_hi);
        float sum_lo = 0.f, sum_hi = 0.f;
        #pragma unroll
        for (int nt = 0; nt < 8; nt++) {
            float p0 = __expf(sacc[nt][0] - mx_lo);
            float p1 = __expf(sacc[nt][1] - mx_lo);
            float p2 = __expf(sacc[nt][2] - mx_hi);
            float p3 = __expf(sacc[nt][3] - mx_hi);
            sum_lo += p0 + p1; sum_hi += p2 + p3;
            int col = nt * 8 + 2 * (lane & 3);
            float2 w0 = {rtf(p0), rtf(p1)};
            float2 w1 = {rtf(p2), rtf(p3)};
            *(float2*)(Pw + (lane >> 2) * PST + col) = w0;
            *(float2*)(Pw + ((lane >> 2) + 8) * PST + col) = w1;
        }
        #pragma unroll
        for (int o = 1; o <= 2; o <<= 1) {
            sum_lo += __shfl_xor_sync(0xffffffffu, sum_lo, o);
            sum_hi += __shfl_xor_sync(0xffffffffu, sum_hi, o);
        }
        l_lo = l_lo * f_lo + sum_lo;
        l_hi = l_hi * f_hi + sum_hi;
        m_lo = mx_lo; m_hi = mx_hi;
        __syncwarp();

        #pragma unroll
        for (int nt = 0; nt < 16; nt++) {
            oacc[nt][0] *= f_lo; oacc[nt][1] *= f_lo;
            oacc[nt][2] *= f_hi; oacc[nt][3] *= f_hi;
        }
        #pragma unroll
        for (int kk = 0; kk < 8; kk++) {
            uint32_t af[4];
            const float* pa = Pw + (lane >> 2) * PST + kk * 8 + (lane & 3);
            af[0] = __float_as_uint(pa[0]);
            af[1] = __float_as_uint(pa[8 * PST]);
            af[2] = __float_as_uint(pa[4]);
            af[3] = __float_as_uint(pa[8 * PST + 4]);
            const float* vrow0 = Vs + (kk * 8 + (lane & 3)) * VST + (lane >> 2);
            const float* vrow1 = vrow0 + 4 * VST;
            #pragma unroll
            for (int nt = 0; nt < 16; nt++) {
                uint32_t b0 = __float_as_uint(vrow0[nt * 8]);
                uint32_t b1 = __float_as_uint(vrow1[nt * 8]);
                asm volatile(
                    "mma.sync.aligned.m16n8k8.row.col.f32.tf32.tf32.f32 "
                    "{%0,%1,%2,%3}, {%4,%5,%6,%7}, {%8,%9}, {%0,%1,%2,%3};"
                    : "+f"(oacc[nt][0]), "+f"(oacc[nt][1]),
                      "+f"(oacc[nt][2]), "+f"(oacc[nt][3])
                    : "r"(af[0]), "r"(af[1]), "r"(af[2]), "r"(af[3]),
                      "r"(b0), "r"(b1));
            }
        }
        __syncthreads();
    }

    // epilogue: normalize + tf32-round (g_o feeds the out-proj GEMM)
    float inv_lo = 1.f / l_lo, inv_hi = 1.f / l_hi;
    int r = qt * 64 + wid * 16 + (lane >> 2);
    float* ob0 = g_o + ((size_t)b * SEQ + r) * INNER + h * HDIM;
    float* ob1 = g_o + ((size_t)b * SEQ + r + 8) * INNER + h * HDIM;
    #pragma unroll
    for (int nt = 0; nt < 16; nt++) {
        int col = nt * 8 + 2 * (lane & 3);
        float2 v0 = {rtf(oacc[nt][0] * inv_lo), rtf(oacc[nt][1] * inv_lo)};
        float2 v1 = {rtf(oacc[nt][2] * inv_hi), rtf(oacc[nt][3] * inv_hi)};
        *(float2*)(ob0 + col) = v0;
        *(float2*)(ob1 + col) = v1;
    }
}

// ---------------- host ----------------
extern "C" void kernel_launch(void* const* d_in, const int* in_sizes, int n_in,
                              void* d_out, int out_size) {
    const float* hid   = (const float*)d_in[0];
    const float* enc   = (const float*)d_in[1];
    const float* cosb  = (const float*)d_in[2];
    const float* sinb  = (const float*)d_in[3];
    const float* w_qkv = (const float*)d_in[4];
    const float* b_qkv = (const float*)d_in[5];
    const float* w_out = (const float*)d_in[6];
    const float* b_out = (const float*)d_in[7];
    float* out = (float*)d_out;

    float *xp, *qkvp, *op, *wqp, *wop;
    cudaGetSymbolAddress((void**)&xp,   g_x);
    cudaGetSymbolAddress((void**)&qkvp, g_qkv);
    cudaGetSymbolAddress((void**)&op,   g_o);
    cudaGetSymbolAddress((void**)&wqp,  g_wq);
    cudaGetSymbolAddress((void**)&wop,  g_wo);

    static bool attr_set = false;
    if (!attr_set) {
        cudaFuncSetAttribute(mma_gemm<0>, cudaFuncAttributeMaxDynamicSharedMemorySize,
                             (int)GEMM_SMEM);
        cudaFuncSetAttribute(mma_gemm<1>, cudaFuncAttributeMaxDynamicSharedMemorySize,
                             (int)GEMM_SMEM);
        cudaFuncSetAttribute(attn_tc_kernel, cudaFuncAttributeMaxDynamicSharedMemorySize,
                             (int)ATT_SMEM);
        attr_set = true;
    }

    // 0. round weights to tf32 (bandwidth-bound, ~60us)
    {
        int n4q = DMODEL * 3 * INNER / 4;
        cvtw_kernel<<<(n4q + 255) / 256, 256>>>(w_qkv, wqp, n4q);
        int n4o = INNER * DMODEL / 4;
        cvtw_kernel<<<(n4o + 255) / 256, 256>>>(w_out, wop, n4o);
    }
    // 1. concat (+round)
    {
        int total = ROWS * DMODEL / 4;
        concat_kernel<<<(total + 255) / 256, 256>>>(hid, enc);
    }
    // 2. qkv gemm
    {
        dim3 grid(3 * INNER / 128, ROWS / 128);
        mma_gemm<0><<<grid, 256, GEMM_SMEM>>>(ROWS, 3 * INNER, DMODEL,
                                              xp, wqp, b_qkv, qkvp);
    }
    // 3. LN + RoPE (+round)
    {
        int warps = BATCH * SEQ * HEADS;
        ln_rope_kernel<<<(warps + 7) / 8, 256>>>(cosb, sinb);
    }
    // 4. attention
    {
        dim3 grid(SEQ / 64, HEADS, BATCH);
        attn_tc_kernel<<<grid, 128, ATT_SMEM>>>();
    }
    // 5. out proj with row remap
    {
        dim3 grid(DMODEL / 128, ROWS / 128);
        mma_gemm<1><<<grid, 256, GEMM_SMEM>>>(ROWS, DMODEL, DMODEL,
                                              op, wop, b_out, out);
    }
}